// round 11
// baseline (speedup 1.0000x reference)
#include <cuda_runtime.h>
#include <cuda_fp16.h>
#include <stdint.h>

// ============================================================================
// y[8192,11008] = x[8192,4096] @ (W * blockscale)[11008,4096]^T   (fp32 io)
// fp32 -> fp16 convert (W dequantized), single-pass fp16 mma.sync GEMM with
// fp32 accumulation. PERSISTENT CTAs (atomic tile ticket), CTA tile 128x128,
// 128 threads (4 warps, 64x64 warp tiles), BK=64, 3-stage cp.async ring that
// runs CONTINUOUSLY across tile boundaries (prefetches next tile's first
// chunks under the current tile's tail + epilogue), 2 CTAs/SM.
// ============================================================================

#define MTOT 8192
#define NTOT 11008
#define KTOT 4096

#define BM 128
#define BN 128
#define BK 64
#define STAGES 3
#define GRID_M (MTOT / BM)           // 64
#define GRID_N (NTOT / BN)           // 86
#define NBLOCKS (GRID_M * GRID_N)    // 5504
#define GROUP_M 8

#define A_BYTES (BM * BK * 2)        // 16 KB
#define B_BYTES (BN * BK * 2)        // 16 KB
#define STAGE_BYTES (A_BYTES + B_BYTES)         // 32 KB
#define SMEM_TILES (STAGES * STAGE_BYTES)       // 96 KB
#define SMEM_TOTAL (SMEM_TILES + 128)           // + ticket slot
static_assert(2 * SMEM_TOTAL <= 227 * 1024, "smem too big for 2 CTAs");

#define KITERS (KTOT / BK)           // 64

// ---- fp16 scratch + tile ticket (static device globals) ----
__device__ __align__(256) __half g_x[(size_t)MTOT * KTOT];   // 64 MB
__device__ __align__(256) __half g_w[(size_t)NTOT * KTOT];   // 90 MB
__device__ unsigned g_ticket;

// ============================================================================
// PTX helpers
// ============================================================================
__device__ __forceinline__ uint32_t smem_u32(const void* p) {
    uint32_t a;
    asm("{ .reg .u64 t; cvta.to.shared.u64 t, %1; cvt.u32.u64 %0, t; }"
        : "=r"(a) : "l"(p));
    return a;
}

#define CP_ASYNC16(dst, src) \
    asm volatile("cp.async.cg.shared.global [%0], [%1], 16;" \
        :: "r"(dst), "l"(src) : "memory")
#define CP_COMMIT() asm volatile("cp.async.commit_group;" ::: "memory")
template <int N>
__device__ __forceinline__ void cp_wait() {
    asm volatile("cp.async.wait_group %0;" :: "n"(N) : "memory");
}

__device__ __forceinline__ void ldsm_x4(uint32_t& r0, uint32_t& r1,
                                        uint32_t& r2, uint32_t& r3, uint32_t a) {
    asm volatile("ldmatrix.sync.aligned.m8n8.x4.shared.b16 {%0,%1,%2,%3}, [%4];"
        : "=r"(r0), "=r"(r1), "=r"(r2), "=r"(r3) : "r"(a));
}

__device__ __forceinline__ void mma16816(float* d, uint32_t a0, uint32_t a1,
                                         uint32_t a2, uint32_t a3,
                                         uint32_t b0, uint32_t b1) {
    asm volatile(
        "mma.sync.aligned.m16n8k16.row.col.f32.f16.f16.f32 "
        "{%0,%1,%2,%3}, {%4,%5,%6,%7}, {%8,%9}, {%0,%1,%2,%3};"
        : "+f"(d[0]), "+f"(d[1]), "+f"(d[2]), "+f"(d[3])
        : "r"(a0), "r"(a1), "r"(a2), "r"(a3), "r"(b0), "r"(b1));
}

// streaming (evict-first) 8-byte store
__device__ __forceinline__ void stg_cs_v2(float* p, float x, float y) {
    asm volatile("st.global.cs.v2.f32 [%0], {%1, %2};"
        :: "l"(p), "f"(x), "f"(y) : "memory");
}

// ============================================================================
// Conversion kernels (convert_x also resets the tile ticket)
// ============================================================================
__global__ void convert_x_kernel(const float4* __restrict__ x) {
    if (blockIdx.x == 0 && threadIdx.x == 0) g_ticket = 0;
    const size_t n4 = (size_t)MTOT * KTOT / 4;
    __half2* dst = reinterpret_cast<__half2*>(g_x);
    for (size_t i = (size_t)blockIdx.x * blockDim.x + threadIdx.x; i < n4;
         i += (size_t)gridDim.x * blockDim.x) {
        float4 v = x[i];
        dst[2 * i]     = __floats2half2_rn(v.x, v.y);
        dst[2 * i + 1] = __floats2half2_rn(v.z, v.w);
    }
}

__global__ void convert_w_kernel(const float4* __restrict__ w,
                                 const float* __restrict__ ws) {
    const size_t n4 = (size_t)NTOT * KTOT / 4;
    __half2* dst = reinterpret_cast<__half2*>(g_w);
    for (size_t i = (size_t)blockIdx.x * blockDim.x + threadIdx.x; i < n4;
         i += (size_t)gridDim.x * blockDim.x) {
        size_t e = 4 * i;
        int row = (int)(e >> 12);         // / 4096
        int col = (int)(e & 4095);
        float s = ws[(row >> 7) * (KTOT / 128) + (col >> 7)];
        float4 v = w[i];
        dst[2 * i]     = __floats2half2_rn(v.x * s, v.y * s);
        dst[2 * i + 1] = __floats2half2_rn(v.z * s, v.w * s);
    }
}

// ============================================================================
// Persistent GEMM
// ============================================================================
__device__ __forceinline__ void tile_coords(int pid, int& m0, int& n0) {
    int group = pid / (GROUP_M * GRID_N);
    int local = pid - group * (GROUP_M * GRID_N);
    m0 = (group * GROUP_M + (local % GROUP_M)) * BM;
    n0 = (local / GROUP_M) * BN;
}

__global__ void __launch_bounds__(128, 2)
gemm_kernel(float* __restrict__ out) {
    extern __shared__ char smem[];
    const uint32_t sb = smem_u32(smem);
    unsigned* tick = reinterpret_cast<unsigned*>(smem + SMEM_TILES);
    const int tid = threadIdx.x;
    const int lane = tid & 31;
    const int wid = tid >> 5;       // 0..3
    const int wm = wid & 1;
    const int wn = wid >> 1;

    // ---- per-lane ldmatrix addressing (XOR swizzle on 128B rows) ----
    uint32_t aOff[4], aSwz[4];
    #pragma unroll
    for (int mt = 0; mt < 4; mt++) {
        uint32_t r = wm * 64 + mt * 16 + (lane & 15);
        aOff[mt] = r * 128;
        aSwz[mt] = (r & 7) << 4;
    }
    const uint32_t aColB = (lane >> 4) * 16;

    const int bg = lane >> 3;
    uint32_t bOff[4], bSwz[4];
    #pragma unroll
    for (int p = 0; p < 4; p++) {
        uint32_t r = wn * 64 + p * 16 + ((bg >> 1) << 3) + (lane & 7);
        bOff[p] = r * 128;
        bSwz[p] = (r & 7) << 4;
    }
    const uint32_t bColB = (bg & 1) * 16;

    // ---- producer per-thread constant offsets ----
    const uint32_t t8 = (uint32_t)(tid >> 3);
    const uint32_t c8 = (uint32_t)(tid & 7);
    const uint32_t dstOff = t8 * 128 + ((c8 ^ (t8 & 7)) << 4);
    const size_t srcOff = (size_t)t8 * (KTOT * 2) + c8 * 16;

    auto issue_copies = [&](const char* aT, const char* bT, int ktl, int s) {
        const uint32_t aB = sb + s * STAGE_BYTES;
        const uint32_t bB = aB + A_BYTES;
        const char* aP = aT + srcOff + (size_t)ktl * 128;
        const char* bP = bT + srcOff + (size_t)ktl * 128;
        #pragma unroll
        for (int i = 0; i < 8; i++)
            CP_ASYNC16(aB + dstOff + i * 2048, aP + (size_t)i * 16 * (KTOT * 2));
        #pragma unroll
        for (int i = 0; i < 8; i++)
            CP_ASYNC16(bB + dstOff + i * 2048, bP + (size_t)i * 16 * (KTOT * 2));
    };

    uint32_t a[4][4], b[8][2];
    auto load_frags = [&](uint32_t aBase, uint32_t kb) {
        const uint32_t bBase = aBase + A_BYTES;
        #pragma unroll
        for (int mt = 0; mt < 4; mt++)
            ldsm_x4(a[mt][0], a[mt][1], a[mt][2], a[mt][3],
                    aBase + aOff[mt] + ((aColB + kb) ^ aSwz[mt]));
        #pragma unroll
        for (int p = 0; p < 4; p++) {
            uint32_t r0, r1, r2, r3;
            ldsm_x4(r0, r1, r2, r3,
                    bBase + bOff[p] + ((bColB + kb) ^ bSwz[p]));
            b[2 * p][0] = r0;     b[2 * p][1] = r1;
            b[2 * p + 1][0] = r2; b[2 * p + 1][1] = r3;
        }
    };

    float acc[4][8][4];
    auto do_mma = [&]() {
        #pragma unroll
        for (int mt = 0; mt < 4; mt++)
            #pragma unroll
            for (int nt = 0; nt < 8; nt++)
                mma16816(acc[mt][nt], a[mt][0], a[mt][1], a[mt][2], a[mt][3],
                         b[nt][0], b[nt][1]);
    };

    // ---- initial tile grab ----
    if (tid == 0) *tick = atomicAdd(&g_ticket, 1u);
    __syncthreads();
    int tile = (int)*tick;
    if (tile >= NBLOCKS) return;     // (grid <= NBLOCKS, shouldn't happen)

    int m0, n0;
    tile_coords(tile, m0, n0);
    const char* aG = (const char*)g_x + (size_t)m0 * KTOT * 2;
    const char* bG = (const char*)g_w + (size_t)n0 * KTOT * 2;

    // ---- prologue: chunks 0,1 of first tile ----
    issue_copies(aG, bG, 0, 0); CP_COMMIT();
    issue_copies(aG, bG, 1, 1); CP_COMMIT();

    int s_cur = 0, s_nxt = 2;
    int nxt = NBLOCKS;               // next tile id (valid from kt==62)
    int m0n = 0, n0n = 0;
    const char *aGn = aG, *bGn = bG;

    // ---- persistent tile loop ----
    for (;;) {
        #pragma unroll
        for (int mt = 0; mt < 4; mt++)
            #pragma unroll
            for (int nt = 0; nt < 8; nt++)
                #pragma unroll
                for (int i = 0; i < 4; i++) acc[mt][nt][i] = 0.f;

        for (int kt = 0; kt < KITERS; kt++) {
            cp_wait<1>();            // chunk kt arrived (kt+1 in flight)
            __syncthreads();

            // grab NEXT tile's ticket early; read 62 barriers later
            if (kt == 0 && tid == 0) *tick = atomicAdd(&g_ticket, 1u);

            const uint32_t base = sb + s_cur * STAGE_BYTES;
            load_frags(base, 0);     // frags first: HMMA restarts early

            if (kt < KITERS - 2) {
                issue_copies(aG, bG, kt + 2, s_nxt);
            } else {
                if (kt == KITERS - 2) {          // read ticket once
                    nxt = (int)*tick;
                    if (nxt < NBLOCKS) {
                        tile_coords(nxt, m0n, n0n);
                        aGn = (const char*)g_x + (size_t)m0n * KTOT * 2;
                        bGn = (const char*)g_w + (size_t)n0n * KTOT * 2;
                    }
                }
                if (nxt < NBLOCKS)               // prefetch next tile ch 0/1
                    issue_copies(aGn, bGn, kt - (KITERS - 2), s_nxt);
            }
            CP_COMMIT();             // always commit (keeps group accounting)

            do_mma();
            load_frags(base, 32); do_mma();
            load_frags(base, 64); do_mma();
            load_frags(base, 96); do_mma();

            s_cur = (s_cur == 2) ? 0 : s_cur + 1;
            s_nxt = (s_nxt == 2) ? 0 : s_nxt + 1;
        }

        // ---- epilogue (overlaps next tile's in-flight cp.async) ----
        const int rq = lane >> 2;
        const int cq = (lane & 3) * 2;
        #pragma unroll
        for (int mt = 0; mt < 4; mt++) {
            const int rbase = m0 + wm * 64 + mt * 16 + rq;
            #pragma unroll
            for (int nt = 0; nt < 8; nt++) {
                const int col = n0 + wn * 64 + nt * 8 + cq;
                stg_cs_v2(out + (size_t)rbase * NTOT + col,
                          acc[mt][nt][0], acc[mt][nt][1]);
                stg_cs_v2(out + (size_t)(rbase + 8) * NTOT + col,
                          acc[mt][nt][2], acc[mt][nt][3]);
            }
        }

        if (nxt >= NBLOCKS) break;
        tile = nxt; m0 = m0n; n0 = n0n; aG = aGn; bG = bGn;
    }
}

// ============================================================================
// Launch
// ============================================================================
extern "C" void kernel_launch(void* const* d_in, const int* in_sizes, int n_in,
                              void* d_out, int out_size) {
    const float* x  = (const float*)d_in[0];
    const float* w  = (const float*)d_in[1];
    const float* ws = (const float*)d_in[2];
    float* out = (float*)d_out;

    convert_x_kernel<<<2048, 256>>>(reinterpret_cast<const float4*>(x));
    convert_w_kernel<<<2048, 256>>>(reinterpret_cast<const float4*>(w), ws);

    int sms = 148;
    cudaDeviceGetAttribute(&sms, cudaDevAttrMultiProcessorCount, 0);
    int grid = 2 * sms;
    if (grid > NBLOCKS) grid = NBLOCKS;

    cudaFuncSetAttribute(gemm_kernel,
                         cudaFuncAttributeMaxDynamicSharedMemorySize, SMEM_TOTAL);
    gemm_kernel<<<grid, 128, SMEM_TOTAL>>>(out);
}

// round 13
// speedup vs baseline: 1.0850x; 1.0850x over previous
#include <cuda_runtime.h>
#include <cuda_fp16.h>
#include <stdint.h>

// ============================================================================
// y[8192,11008] = x[8192,4096] @ (W * blockscale)[11008,4096]^T   (fp32 io)
// fp32 -> fp16 convert (W dequantized by 128x128 block scale) in ONE fused
// kernel with 16B stores, then single-pass fp16 mma.sync GEMM with fp32
// accumulation. CTA tile 128x128, 128 threads (4 warps, 64x64 warp tiles),
// BK=64, 3-stage cp.async ring, 2 CTAs/SM, 1 barrier per K-chunk,
// streaming (evict-first) output stores.   [GEMM identical to round-10 best]
// ============================================================================

#define MTOT 8192
#define NTOT 11008
#define KTOT 4096

#define BM 128
#define BN 128
#define BK 64
#define STAGES 3
#define GRID_M (MTOT / BM)           // 64
#define GRID_N (NTOT / BN)           // 86
#define NBLOCKS (GRID_M * GRID_N)    // 5504
#define GROUP_M 8

#define A_BYTES (BM * BK * 2)        // 16 KB
#define B_BYTES (BN * BK * 2)        // 16 KB
#define STAGE_BYTES (A_BYTES + B_BYTES)         // 32 KB
#define SMEM_TOTAL (STAGES * STAGE_BYTES)       // 96 KB -> 2 CTAs = 192 KB/SM
static_assert(2 * SMEM_TOTAL <= 227 * 1024, "smem too big for 2 CTAs");

#define KITERS (KTOT / BK)           // 64

// ---- fp16 scratch (static device globals; dynamic alloc forbidden) ----
__device__ __align__(256) __half g_x[(size_t)MTOT * KTOT];   // 64 MB
__device__ __align__(256) __half g_w[(size_t)NTOT * KTOT];   // 90 MB

// ============================================================================
// PTX helpers
// ============================================================================
__device__ __forceinline__ uint32_t smem_u32(const void* p) {
    uint32_t a;
    asm("{ .reg .u64 t; cvta.to.shared.u64 t, %1; cvt.u32.u64 %0, t; }"
        : "=r"(a) : "l"(p));
    return a;
}

#define CP_ASYNC16(dst, src) \
    asm volatile("cp.async.cg.shared.global [%0], [%1], 16;" \
        :: "r"(dst), "l"(src) : "memory")
#define CP_COMMIT() asm volatile("cp.async.commit_group;" ::: "memory")
template <int N>
__device__ __forceinline__ void cp_wait() {
    asm volatile("cp.async.wait_group %0;" :: "n"(N) : "memory");
}

__device__ __forceinline__ void ldsm_x4(uint32_t& r0, uint32_t& r1,
                                        uint32_t& r2, uint32_t& r3, uint32_t a) {
    asm volatile("ldmatrix.sync.aligned.m8n8.x4.shared.b16 {%0,%1,%2,%3}, [%4];"
        : "=r"(r0), "=r"(r1), "=r"(r2), "=r"(r3) : "r"(a));
}

__device__ __forceinline__ void mma16816(float* d, uint32_t a0, uint32_t a1,
                                         uint32_t a2, uint32_t a3,
                                         uint32_t b0, uint32_t b1) {
    asm volatile(
        "mma.sync.aligned.m16n8k16.row.col.f32.f16.f16.f32 "
        "{%0,%1,%2,%3}, {%4,%5,%6,%7}, {%8,%9}, {%0,%1,%2,%3};"
        : "+f"(d[0]), "+f"(d[1]), "+f"(d[2]), "+f"(d[3])
        : "r"(a0), "r"(a1), "r"(a2), "r"(a3), "r"(b0), "r"(b1));
}

// streaming (evict-first) 8-byte store
__device__ __forceinline__ void stg_cs_v2(float* p, float x, float y) {
    asm volatile("st.global.cs.v2.f32 [%0], {%1, %2};"
        :: "l"(p), "f"(x), "f"(y) : "memory");
}

// bit-reinterpret __half2 -> uint32_t (no such stock intrinsic)
__device__ __forceinline__ uint32_t h2_as_u32(__half2 h) {
    return *reinterpret_cast<uint32_t*>(&h);
}

// ============================================================================
// Fused conversion kernel: 16B-granule work items.
//   item i < NX8  : x[8 floats]  -> g_x[8 halves]
//   item i >= NX8 : w[8 floats] * blockscale -> g_w[8 halves]
// ============================================================================
#define NX8 ((size_t)MTOT * KTOT / 8)    // 4M items
#define NW8 ((size_t)NTOT * KTOT / 8)    // ~5.6M items
#define NTOTAL8 (NX8 + NW8)

__global__ void convert_fused_kernel(const float4* __restrict__ x,
                                     const float4* __restrict__ w,
                                     const float* __restrict__ ws) {
    uint4* gx = reinterpret_cast<uint4*>(g_x);
    uint4* gw = reinterpret_cast<uint4*>(g_w);
    for (size_t i = (size_t)blockIdx.x * blockDim.x + threadIdx.x; i < NTOTAL8;
         i += (size_t)gridDim.x * blockDim.x) {
        if (i < NX8) {
            float4 v0 = x[2 * i];
            float4 v1 = x[2 * i + 1];
            uint4 o;
            o.x = h2_as_u32(__floats2half2_rn(v0.x, v0.y));
            o.y = h2_as_u32(__floats2half2_rn(v0.z, v0.w));
            o.z = h2_as_u32(__floats2half2_rn(v1.x, v1.y));
            o.w = h2_as_u32(__floats2half2_rn(v1.z, v1.w));
            gx[i] = o;
        } else {
            size_t j = i - NX8;                    // w item
            size_t e = 8 * j;                      // element index
            int row = (int)(e >> 12);              // / 4096
            int col = (int)(e & 4095);
            float s = ws[(row >> 7) * (KTOT / 128) + (col >> 7)];
            float4 v0 = w[2 * j];
            float4 v1 = w[2 * j + 1];
            uint4 o;
            o.x = h2_as_u32(__floats2half2_rn(v0.x * s, v0.y * s));
            o.y = h2_as_u32(__floats2half2_rn(v0.z * s, v0.w * s));
            o.z = h2_as_u32(__floats2half2_rn(v1.x * s, v1.y * s));
            o.w = h2_as_u32(__floats2half2_rn(v1.z * s, v1.w * s));
            gw[j] = o;
        }
    }
}

// ============================================================================
// GEMM (identical to round-10 best)
// ============================================================================
__global__ void __launch_bounds__(128, 2)
gemm_kernel(float* __restrict__ out) {
    extern __shared__ char smem[];
    const uint32_t sb = smem_u32(smem);
    const int tid = threadIdx.x;
    const int lane = tid & 31;
    const int wid = tid >> 5;       // 0..3
    const int wm = wid & 1;         // warp row (0..1) -> 64 M-rows
    const int wn = wid >> 1;        // warp col (0..1) -> 64 N-cols

    // ---- tile rasterization (GROUP_M supertiles for L2 reuse) ----
    int pid = blockIdx.x;
    int group = pid / (GROUP_M * GRID_N);
    int local = pid - group * (GROUP_M * GRID_N);
    int pid_m = group * GROUP_M + (local % GROUP_M);
    int pid_n = local / GROUP_M;
    const int m0 = pid_m * BM;
    const int n0 = pid_n * BN;

    const char* aG = (const char*)g_x + (size_t)m0 * KTOT * 2;
    const char* bG = (const char*)g_w + (size_t)n0 * KTOT * 2;

    // ---- per-lane ldmatrix addressing (XOR swizzle on 128B rows) ----
    uint32_t aOff[4], aSwz[4];
    #pragma unroll
    for (int mt = 0; mt < 4; mt++) {
        uint32_t r = wm * 64 + mt * 16 + (lane & 15);
        aOff[mt] = r * 128;
        aSwz[mt] = (r & 7) << 4;
    }
    const uint32_t aColB = (lane >> 4) * 16;

    const int bg = lane >> 3;
    uint32_t bOff[4], bSwz[4];
    #pragma unroll
    for (int p = 0; p < 4; p++) {
        uint32_t r = wn * 64 + p * 16 + ((bg >> 1) << 3) + (lane & 7);
        bOff[p] = r * 128;
        bSwz[p] = (r & 7) << 4;
    }
    const uint32_t bColB = (bg & 1) * 16;

    float acc[4][8][4];
    #pragma unroll
    for (int mt = 0; mt < 4; mt++)
        #pragma unroll
        for (int nt = 0; nt < 8; nt++)
            #pragma unroll
            for (int i = 0; i < 4; i++) acc[mt][nt][i] = 0.f;

    // ---- producer: per-thread constant offsets ----
    const uint32_t t8 = (uint32_t)(tid >> 3);
    const uint32_t c8 = (uint32_t)(tid & 7);
    const uint32_t dstOff = t8 * 128 + ((c8 ^ (t8 & 7)) << 4);
    const size_t srcOff = (size_t)t8 * (KTOT * 2) + c8 * 16;

    auto issue_stage = [&](int kt, int s) {
        const uint32_t aB = sb + s * STAGE_BYTES;
        const uint32_t bB = aB + A_BYTES;
        const char* aP = aG + srcOff + (size_t)kt * 128;
        const char* bP = bG + srcOff + (size_t)kt * 128;
        #pragma unroll
        for (int i = 0; i < 8; i++)      // A: 8 granules/thread (16 rows apart)
            CP_ASYNC16(aB + dstOff + i * 2048,
                       aP + (size_t)i * 16 * (KTOT * 2));
        #pragma unroll
        for (int i = 0; i < 8; i++)      // B: 8 granules/thread
            CP_ASYNC16(bB + dstOff + i * 2048,
                       bP + (size_t)i * 16 * (KTOT * 2));
        CP_COMMIT();
    };

    uint32_t a[4][4], b[8][2];
    auto load_frags = [&](uint32_t aBase, uint32_t kb) {
        const uint32_t bBase = aBase + A_BYTES;
        #pragma unroll
        for (int mt = 0; mt < 4; mt++)
            ldsm_x4(a[mt][0], a[mt][1], a[mt][2], a[mt][3],
                    aBase + aOff[mt] + ((aColB + kb) ^ aSwz[mt]));
        #pragma unroll
        for (int p = 0; p < 4; p++) {
            uint32_t r0, r1, r2, r3;
            ldsm_x4(r0, r1, r2, r3,
                    bBase + bOff[p] + ((bColB + kb) ^ bSwz[p]));
            b[2 * p][0] = r0;     b[2 * p][1] = r1;
            b[2 * p + 1][0] = r2; b[2 * p + 1][1] = r3;
        }
    };
    auto do_mma = [&]() {
        #pragma unroll
        for (int mt = 0; mt < 4; mt++)
            #pragma unroll
            for (int nt = 0; nt < 8; nt++)
                mma16816(acc[mt][nt], a[mt][0], a[mt][1], a[mt][2], a[mt][3],
                         b[nt][0], b[nt][1]);
    };

    // ---- prologue: STAGES-1 = 2 chunks in flight ----
    issue_stage(0, 0);
    issue_stage(1, 1);

    // ---- mainloop: ONE barrier per chunk (trailing barrier proven redundant)
    int s_cur = 0, s_nxt = 2;
    for (int kt = 0; kt < KITERS; kt++) {
        cp_wait<1>();                    // chunk kt arrived (kt+1 in flight)
        __syncthreads();

        const uint32_t base = sb + s_cur * STAGE_BYTES;

        load_frags(base, 0);             // frags first: HMMA restarts early
        if (kt + 2 < KITERS) issue_stage(kt + 2, s_nxt);
        do_mma();
        load_frags(base, 32); do_mma();
        load_frags(base, 64); do_mma();
        load_frags(base, 96); do_mma();

        s_cur = (s_cur == 2) ? 0 : s_cur + 1;
        s_nxt = (s_nxt == 2) ? 0 : s_nxt + 1;
    }

    // ---- epilogue: streaming stores (output never re-read; keep L2 for B) ----
    const int rq = lane >> 2;           // 0..7
    const int cq = (lane & 3) * 2;      // 0,2,4,6
    #pragma unroll
    for (int mt = 0; mt < 4; mt++) {
        const int rbase = m0 + wm * 64 + mt * 16 + rq;
        #pragma unroll
        for (int nt = 0; nt < 8; nt++) {
            const int col = n0 + wn * 64 + nt * 8 + cq;
            stg_cs_v2(out + (size_t)rbase * NTOT + col,
                      acc[mt][nt][0], acc[mt][nt][1]);
            stg_cs_v2(out + (size_t)(rbase + 8) * NTOT + col,
                      acc[mt][nt][2], acc[mt][nt][3]);
        }
    }
}

// ============================================================================
// Launch
// ============================================================================
extern "C" void kernel_launch(void* const* d_in, const int* in_sizes, int n_in,
                              void* d_out, int out_size) {
    const float* x  = (const float*)d_in[0];
    const float* w  = (const float*)d_in[1];
    const float* ws = (const float*)d_in[2];
    float* out = (float*)d_out;

    convert_fused_kernel<<<148 * 16, 256>>>(
        reinterpret_cast<const float4*>(x),
        reinterpret_cast<const float4*>(w), ws);

    cudaFuncSetAttribute(gemm_kernel,
                         cudaFuncAttributeMaxDynamicSharedMemorySize, SMEM_TOTAL);
    gemm_kernel<<<NBLOCKS, 128, SMEM_TOTAL>>>(out);
}

// round 14
// speedup vs baseline: 1.0859x; 1.0009x over previous
#include <cuda_runtime.h>
#include <cuda_fp16.h>
#include <stdint.h>

// ============================================================================
// y[8192,11008] = x[8192,4096] @ (W * blockscale)[11008,4096]^T   (fp32 io)
// Fused fp32->fp16 convert (W dequantized), single-pass fp16 mma.sync GEMM,
// fp32 accumulation. CTA tile 128x128, 128 threads (4 warps, 64x64 warp
// tiles), BK=64, 3-stage cp.async ring, 2 CTAs/SM.
// NEW: odd CTAs consume K-chunks in rotated order (start at 32, wrap) to
// de-phase the two co-resident CTAs' barrier/dependency stalls, keeping the
// SM's tensor pipes fed; A/B LDSMs interleaved so the first MMA's operands
// arrive after 2 LDSMs.
// ============================================================================

#define MTOT 8192
#define NTOT 11008
#define KTOT 4096

#define BM 128
#define BN 128
#define BK 64
#define STAGES 3
#define GRID_M (MTOT / BM)           // 64
#define GRID_N (NTOT / BN)           // 86
#define NBLOCKS (GRID_M * GRID_N)    // 5504
#define GROUP_M 8

#define A_BYTES (BM * BK * 2)        // 16 KB
#define B_BYTES (BN * BK * 2)        // 16 KB
#define STAGE_BYTES (A_BYTES + B_BYTES)         // 32 KB
#define SMEM_TOTAL (STAGES * STAGE_BYTES)       // 96 KB -> 2 CTAs = 192 KB/SM
static_assert(2 * SMEM_TOTAL <= 227 * 1024, "smem too big for 2 CTAs");

#define KITERS (KTOT / BK)           // 64

// ---- fp16 scratch (static device globals; dynamic alloc forbidden) ----
__device__ __align__(256) __half g_x[(size_t)MTOT * KTOT];   // 64 MB
__device__ __align__(256) __half g_w[(size_t)NTOT * KTOT];   // 90 MB

// ============================================================================
// PTX helpers
// ============================================================================
__device__ __forceinline__ uint32_t smem_u32(const void* p) {
    uint32_t a;
    asm("{ .reg .u64 t; cvta.to.shared.u64 t, %1; cvt.u32.u64 %0, t; }"
        : "=r"(a) : "l"(p));
    return a;
}

#define CP_ASYNC16(dst, src) \
    asm volatile("cp.async.cg.shared.global [%0], [%1], 16;" \
        :: "r"(dst), "l"(src) : "memory")
#define CP_COMMIT() asm volatile("cp.async.commit_group;" ::: "memory")
template <int N>
__device__ __forceinline__ void cp_wait() {
    asm volatile("cp.async.wait_group %0;" :: "n"(N) : "memory");
}

__device__ __forceinline__ void ldsm_x4(uint32_t& r0, uint32_t& r1,
                                        uint32_t& r2, uint32_t& r3, uint32_t a) {
    asm volatile("ldmatrix.sync.aligned.m8n8.x4.shared.b16 {%0,%1,%2,%3}, [%4];"
        : "=r"(r0), "=r"(r1), "=r"(r2), "=r"(r3) : "r"(a));
}

__device__ __forceinline__ void mma16816(float* d, uint32_t a0, uint32_t a1,
                                         uint32_t a2, uint32_t a3,
                                         uint32_t b0, uint32_t b1) {
    asm volatile(
        "mma.sync.aligned.m16n8k16.row.col.f32.f16.f16.f32 "
        "{%0,%1,%2,%3}, {%4,%5,%6,%7}, {%8,%9}, {%0,%1,%2,%3};"
        : "+f"(d[0]), "+f"(d[1]), "+f"(d[2]), "+f"(d[3])
        : "r"(a0), "r"(a1), "r"(a2), "r"(a3), "r"(b0), "r"(b1));
}

// streaming (evict-first) 8-byte store
__device__ __forceinline__ void stg_cs_v2(float* p, float x, float y) {
    asm volatile("st.global.cs.v2.f32 [%0], {%1, %2};"
        :: "l"(p), "f"(x), "f"(y) : "memory");
}

// bit-reinterpret __half2 -> uint32_t
__device__ __forceinline__ uint32_t h2_as_u32(__half2 h) {
    return *reinterpret_cast<uint32_t*>(&h);
}

// ============================================================================
// Fused conversion kernel: 16B-granule work items.
// ============================================================================
#define NX8 ((size_t)MTOT * KTOT / 8)    // 4M items
#define NW8 ((size_t)NTOT * KTOT / 8)    // ~5.6M items
#define NTOTAL8 (NX8 + NW8)

__global__ void convert_fused_kernel(const float4* __restrict__ x,
                                     const float4* __restrict__ w,
                                     const float* __restrict__ ws) {
    uint4* gx = reinterpret_cast<uint4*>(g_x);
    uint4* gw = reinterpret_cast<uint4*>(g_w);
    for (size_t i = (size_t)blockIdx.x * blockDim.x + threadIdx.x; i < NTOTAL8;
         i += (size_t)gridDim.x * blockDim.x) {
        if (i < NX8) {
            float4 v0 = x[2 * i];
            float4 v1 = x[2 * i + 1];
            uint4 o;
            o.x = h2_as_u32(__floats2half2_rn(v0.x, v0.y));
            o.y = h2_as_u32(__floats2half2_rn(v0.z, v0.w));
            o.z = h2_as_u32(__floats2half2_rn(v1.x, v1.y));
            o.w = h2_as_u32(__floats2half2_rn(v1.z, v1.w));
            gx[i] = o;
        } else {
            size_t j = i - NX8;                    // w item
            size_t e = 8 * j;                      // element index
            int row = (int)(e >> 12);              // / 4096
            int col = (int)(e & 4095);
            float s = ws[(row >> 7) * (KTOT / 128) + (col >> 7)];
            float4 v0 = w[2 * j];
            float4 v1 = w[2 * j + 1];
            uint4 o;
            o.x = h2_as_u32(__floats2half2_rn(v0.x * s, v0.y * s));
            o.y = h2_as_u32(__floats2half2_rn(v0.z * s, v0.w * s));
            o.z = h2_as_u32(__floats2half2_rn(v1.x * s, v1.y * s));
            o.w = h2_as_u32(__floats2half2_rn(v1.z * s, v1.w * s));
            gw[j] = o;
        }
    }
}

// ============================================================================
// GEMM
// ============================================================================
__global__ void __launch_bounds__(128, 2)
gemm_kernel(float* __restrict__ out) {
    extern __shared__ char smem[];
    const uint32_t sb = smem_u32(smem);
    const int tid = threadIdx.x;
    const int lane = tid & 31;
    const int wid = tid >> 5;       // 0..3
    const int wm = wid & 1;         // warp row (0..1) -> 64 M-rows
    const int wn = wid >> 1;        // warp col (0..1) -> 64 N-cols

    // ---- tile rasterization (GROUP_M supertiles for L2 reuse) ----
    int pid = blockIdx.x;
    int group = pid / (GROUP_M * GRID_N);
    int local = pid - group * (GROUP_M * GRID_N);
    int pid_m = group * GROUP_M + (local % GROUP_M);
    int pid_n = local / GROUP_M;
    const int m0 = pid_m * BM;
    const int n0 = pid_n * BN;

    // de-phase co-resident CTAs: odd CTAs start K at chunk 32 (wrap mod 64).
    const int krot = (blockIdx.x & 1) ? (KITERS / 2) : 0;

    const char* aG = (const char*)g_x + (size_t)m0 * KTOT * 2;
    const char* bG = (const char*)g_w + (size_t)n0 * KTOT * 2;

    // ---- per-lane ldmatrix addressing (XOR swizzle on 128B rows) ----
    uint32_t aOff[4], aSwz[4];
    #pragma unroll
    for (int mt = 0; mt < 4; mt++) {
        uint32_t r = wm * 64 + mt * 16 + (lane & 15);
        aOff[mt] = r * 128;
        aSwz[mt] = (r & 7) << 4;
    }
    const uint32_t aColB = (lane >> 4) * 16;

    const int bg = lane >> 3;
    uint32_t bOff[4], bSwz[4];
    #pragma unroll
    for (int p = 0; p < 4; p++) {
        uint32_t r = wn * 64 + p * 16 + ((bg >> 1) << 3) + (lane & 7);
        bOff[p] = r * 128;
        bSwz[p] = (r & 7) << 4;
    }
    const uint32_t bColB = (bg & 1) * 16;

    float acc[4][8][4];
    #pragma unroll
    for (int mt = 0; mt < 4; mt++)
        #pragma unroll
        for (int nt = 0; nt < 8; nt++)
            #pragma unroll
            for (int i = 0; i < 4; i++) acc[mt][nt][i] = 0.f;

    // ---- producer: per-thread constant offsets ----
    const uint32_t t8 = (uint32_t)(tid >> 3);
    const uint32_t c8 = (uint32_t)(tid & 7);
    const uint32_t dstOff = t8 * 128 + ((c8 ^ (t8 & 7)) << 4);
    const size_t srcOff = (size_t)t8 * (KTOT * 2) + c8 * 16;

    auto issue_stage = [&](int kt, int s) {   // kt = logical; rotate to physical
        const int kc = (kt + krot) & (KITERS - 1);
        const uint32_t aB = sb + s * STAGE_BYTES;
        const uint32_t bB = aB + A_BYTES;
        const char* aP = aG + srcOff + (size_t)kc * 128;
        const char* bP = bG + srcOff + (size_t)kc * 128;
        #pragma unroll
        for (int i = 0; i < 8; i++)      // A: 8 granules/thread (16 rows apart)
            CP_ASYNC16(aB + dstOff + i * 2048,
                       aP + (size_t)i * 16 * (KTOT * 2));
        #pragma unroll
        for (int i = 0; i < 8; i++)      // B: 8 granules/thread
            CP_ASYNC16(bB + dstOff + i * 2048,
                       bP + (size_t)i * 16 * (KTOT * 2));
        CP_COMMIT();
    };

    uint32_t a[4][4], b[8][2];
    auto load_frags = [&](uint32_t aBase, uint32_t kb) {
        const uint32_t bBase = aBase + A_BYTES;
        // interleave A/B so the first MMA's operands (a[0], b[0]) complete
        // after the first two LDSMs.
        #pragma unroll
        for (int p = 0; p < 4; p++) {
            ldsm_x4(a[p][0], a[p][1], a[p][2], a[p][3],
                    aBase + aOff[p] + ((aColB + kb) ^ aSwz[p]));
            uint32_t r0, r1, r2, r3;
            ldsm_x4(r0, r1, r2, r3,
                    bBase + bOff[p] + ((bColB + kb) ^ bSwz[p]));
            b[2 * p][0] = r0;     b[2 * p][1] = r1;
            b[2 * p + 1][0] = r2; b[2 * p + 1][1] = r3;
        }
    };
    auto do_mma = [&]() {
        #pragma unroll
        for (int mt = 0; mt < 4; mt++)
            #pragma unroll
            for (int nt = 0; nt < 8; nt++)
                mma16816(acc[mt][nt], a[mt][0], a[mt][1], a[mt][2], a[mt][3],
                         b[nt][0], b[nt][1]);
    };

    // ---- prologue: STAGES-1 = 2 chunks in flight ----
    issue_stage(0, 0);
    issue_stage(1, 1);

    // ---- mainloop: ONE barrier per chunk ----
    int s_cur = 0, s_nxt = 2;
    for (int kt = 0; kt < KITERS; kt++) {
        cp_wait<1>();                    // chunk kt arrived (kt+1 in flight)
        __syncthreads();

        const uint32_t base = sb + s_cur * STAGE_BYTES;

        load_frags(base, 0);             // frags first: HMMA restarts early
        if (kt + 2 < KITERS) issue_stage(kt + 2, s_nxt);
        do_mma();
        load_frags(base, 32); do_mma();
        load_frags(base, 64); do_mma();
        load_frags(base, 96); do_mma();

        s_cur = (s_cur == 2) ? 0 : s_cur + 1;
        s_nxt = (s_nxt == 2) ? 0 : s_nxt + 1;
    }

    // ---- epilogue: streaming stores ----
    const int rq = lane >> 2;           // 0..7
    const int cq = (lane & 3) * 2;      // 0,2,4,6
    #pragma unroll
    for (int mt = 0; mt < 4; mt++) {
        const int rbase = m0 + wm * 64 + mt * 16 + rq;
        #pragma unroll
        for (int nt = 0; nt < 8; nt++) {
            const int col = n0 + wn * 64 + nt * 8 + cq;
            stg_cs_v2(out + (size_t)rbase * NTOT + col,
                      acc[mt][nt][0], acc[mt][nt][1]);
            stg_cs_v2(out + (size_t)(rbase + 8) * NTOT + col,
                      acc[mt][nt][2], acc[mt][nt][3]);
        }
    }
}

// ============================================================================
// Launch
// ============================================================================
extern "C" void kernel_launch(void* const* d_in, const int* in_sizes, int n_in,
                              void* d_out, int out_size) {
    const float* x  = (const float*)d_in[0];
    const float* w  = (const float*)d_in[1];
    const float* ws = (const float*)d_in[2];
    float* out = (float*)d_out;

    convert_fused_kernel<<<148 * 16, 256>>>(
        reinterpret_cast<const float4*>(x),
        reinterpret_cast<const float4*>(w), ws);

    cudaFuncSetAttribute(gemm_kernel,
                         cudaFuncAttributeMaxDynamicSharedMemorySize, SMEM_TOTAL);
    gemm_kernel<<<NBLOCKS, 128, SMEM_TOTAL>>>(out);
}